// round 11
// baseline (speedup 1.0000x reference)
#include <cuda_runtime.h>
#include <stdint.h>

// Problem shape is fixed by setup_inputs(): B=64, N=4, H=512, W=512, num=1024.
#define BB 64
#define NPLANES 4
#define HH 512
#define WW 512
#define HWPIX (HH * WW)            // 262144
#define HW4 (HWPIX / 4)            // 65536 float4s per plane
#define WORDS_PER_B (HWPIX / 32)   // 8192
#define CHUNKS 256                 // chunks per batch; chunk = 32 words = 1024 px
#define NUM 1024
#define IDX_ELEMS (BB * NUM * 2)   // 131072 index values

// Scratch (no allocations allowed). g_arrive zero-initialized at module load
// and reset by the sampler block each launch (graph-replay safe).
__device__ uint32_t g_bits[BB * WORDS_PER_B];    // 2 MiB  packed valid bits
__device__ int      g_chunk[BB * CHUNKS];        // 64 KiB popcount per chunk
__device__ int      g_arrive[BB];                // per-batch arrival counters

// ---------------------------------------------------------------------------
// Single fused kernel.
// Phase 1 (every block = one 1024-px chunk of one batch):
//   valid = (sum_n masks) > 0.5 via float4 loads (6.66 TB/s, at the LTS cap),
//   pack to 32 bit-words, block-reduce the chunk popcount.
// Phase 2 (the LAST block to finish in each batch — detected by atomicAdd):
//   scan the batch's 256 chunk counts (L2-hot, just written), then sample all
//   1024 points (4/thread). Runs while later batches still stream masks, so
//   its latency hides under DRAM time; its g_bits reads hit L2.
// Replicates: r = min(int(u*float(cnt)), cnt-1); pos = searchsorted(csum, r+1).
// ---------------------------------------------------------------------------
__global__ __launch_bounds__(256) void k_fused(const float4* __restrict__ m4,
                                               const float* __restrict__ rand_u,
                                               float* __restrict__ out,
                                               int tail_n) {
    int b = blockIdx.x >> 8;                     // batch (256 blocks per batch)
    int gid4 = blockIdx.x * 256 + threadIdx.x;   // float4 index in [0, B*HW/4)
    int p4 = gid4 & (HW4 - 1);
    int t = threadIdx.x;
    int l = t & 31, wid = t >> 5;

    // Tail fill ((H, W) tuple leaves flattened into d_out) — independent.
    if (blockIdx.x == 0) {
        for (int i = t; i < tail_n; i += 256) out[IDX_ELEMS + i] = 512.0f;
    }

    // --- Phase 1: mask -> bits ---
    const float4* base = m4 + (size_t)b * NPLANES * HW4 + p4;
    float4 a0 = base[0];
    float4 a1 = base[HW4];
    float4 a2 = base[2 * HW4];
    float4 a3 = base[3 * HW4];
    // Keep the exact association order that validated bit-exact.
    float sx = ((a0.x + a1.x) + a2.x) + a3.x;
    float sy = ((a0.y + a1.y) + a2.y) + a3.y;
    float sz = ((a0.z + a1.z) + a2.z) + a3.z;
    float sw = ((a0.w + a1.w) + a2.w) + a3.w;
    unsigned nib = (unsigned)(sx > 0.5f)
                 | ((unsigned)(sy > 0.5f) << 1)
                 | ((unsigned)(sz > 0.5f) << 2)
                 | ((unsigned)(sw > 0.5f) << 3);
    unsigned v = nib << ((l & 7) * 4);
    v |= __shfl_xor_sync(0xFFFFFFFFu, v, 1);
    v |= __shfl_xor_sync(0xFFFFFFFFu, v, 2);
    v |= __shfl_xor_sync(0xFFFFFFFFu, v, 4);
    if ((l & 7) == 0) g_bits[gid4 >> 3] = v;     // word = (4*gid4)/32

    // Chunk popcount: block-wide sum of per-thread nibble popcounts.
    __shared__ int wsum[8];
    __shared__ int s_last;
    int c4 = __popc(nib);
#pragma unroll
    for (int off = 16; off; off >>= 1)
        c4 += __shfl_xor_sync(0xFFFFFFFFu, c4, off);
    if (l == 0) wsum[wid] = c4;
    __syncthreads();
    if (t == 0) {
        int s = 0;
#pragma unroll
        for (int i = 0; i < 8; i++) s += wsum[i];
        g_chunk[blockIdx.x] = s;                 // blockIdx.x = b*CHUNKS + chunk
    }

    // --- Arrival protocol (threadfence-reduction pattern) ---
    __threadfence();            // order this thread's global writes
    __syncthreads();            // all threads' fences retired
    if (t == 0) {
        int old = atomicAdd(&g_arrive[b], 1);
        int last = (old == CHUNKS - 1);
        if (last) g_arrive[b] = 0;   // exclusive owner: reset for next replay
        s_last = last;
    }
    __syncthreads();
    if (!s_last) return;
    __threadfence();            // acquire side: see other blocks' bits/counts

    // --- Phase 2: this block samples its whole batch ---
    __shared__ int s_coarse[CHUNKS];
    __shared__ int warp_tot[8];
    __shared__ int s_total;

    int c = g_chunk[b * CHUNKS + t];
    int vv = c;
#pragma unroll
    for (int off = 1; off < 32; off <<= 1) {
        int n = __shfl_up_sync(0xFFFFFFFFu, vv, off);
        if (l >= off) vv += n;
    }
    if (l == 31) warp_tot[wid] = vv;
    __syncthreads();
    int wbase = 0;
#pragma unroll
    for (int i = 0; i < 8; i++) wbase += (i < wid) ? warp_tot[i] : 0;
    s_coarse[t] = wbase + vv - c;        // bits strictly before chunk t
    if (t == 255) s_total = wbase + vv;  // batch total
    __syncthreads();

    int total = s_total;
    const uint4* bwords = reinterpret_cast<const uint4*>(g_bits + (size_t)b * WORDS_PER_B);

    for (int pt = t; pt < NUM; pt += 256) {
        float u = rand_u[b * NUM + pt];

        int pos;
        if (total == 0) {
            // reference: cnt = max(total,1)=1, r=0, searchsorted over all-zero
            // csum for target 1 -> insertion point HW.
            pos = HWPIX;
        } else {
            int cnt = total;
            int r = (int)(u * (float)cnt);   // fp32 RN mul, trunc — matches jnp
            if (r > cnt - 1) r = cnt - 1;
            int tgt = r + 1;                 // want the tgt-th set bit (1-indexed)

            // Coarse: last chunk with (bits before chunk) < tgt.
            int lo = 0, hi = CHUNKS;
#pragma unroll
            for (int s = 0; s < 8; s++) {
                int mid = (lo + hi) >> 1;
                if (s_coarse[mid] < tgt) lo = mid; else hi = mid;
            }
            int k = tgt - s_coarse[lo];      // k-th set bit within chunk, k>=1

            // Load the chunk's 32 bit-words (128 B, MLP=8, L2-hot).
            const uint4* bw = bwords + lo * 8;
            int gi = 0;
            bool found = false;
#pragma unroll
            for (int i = 0; i < 8; i++) {
                uint4 q = bw[i];
                int gs = __popc(q.x) + __popc(q.y) + __popc(q.z) + __popc(q.w);
                if (!found) {
                    if (k > gs) k -= gs;
                    else { gi = i; found = true; }
                }
            }
            uint4 qq = bw[gi];               // re-load: L1 hit
            int w2 = 0;
            uint32_t wrd = qq.x;
            int pc = __popc(qq.x);
            if (k > pc) {
                k -= pc; wrd = qq.y; w2 = 1; pc = __popc(qq.y);
                if (k > pc) {
                    k -= pc; wrd = qq.z; w2 = 2; pc = __popc(qq.z);
                    if (k > pc) { k -= pc; wrd = qq.w; w2 = 3; }
                }
            }
            // Fixed-depth 5-step binary select of the k-th set bit (1-indexed).
            int idx = 0;
            int cc = __popc(wrd & 0xFFFFu);
            if (k > cc) { k -= cc; idx += 16; wrd >>= 16; }
            cc = __popc(wrd & 0xFFu);
            if (k > cc) { k -= cc; idx += 8; wrd >>= 8; }
            cc = __popc(wrd & 0xFu);
            if (k > cc) { k -= cc; idx += 4; wrd >>= 4; }
            cc = __popc(wrd & 0x3u);
            if (k > cc) { k -= cc; idx += 2; wrd >>= 2; }
            cc = wrd & 1u;
            if (k > cc) { idx += 1; }
            pos = lo * 1024 + (gi * 4 + w2) * 32 + idx;
        }

        float2 hw;
        hw.x = (float)(pos / WW);
        hw.y = (float)(pos & (WW - 1));
        *reinterpret_cast<float2*>(out + ((size_t)b * NUM + pt) * 2) = hw;
    }
}

extern "C" void kernel_launch(void* const* d_in, const int* in_sizes, int n_in,
                              void* d_out, int out_size) {
    // Identify inputs by size, robust to metadata ordering.
    const float* masks  = nullptr;   // [64,4,512,512] f32 -> 67,108,864 elems
    const float* rand_u = nullptr;   // [64,1024] f32      -> 65,536 elems
    for (int i = 0; i < n_in; i++) {
        if (in_sizes[i] == BB * NPLANES * HWPIX) masks = (const float*)d_in[i];
        else if (in_sizes[i] == BB * NUM)        rand_u = (const float*)d_in[i];
    }
    if (!masks)  masks  = (const float*)d_in[0];
    if (!rand_u) rand_u = (const float*)d_in[1];
    float* out = (float*)d_out;      // [64,1024,2] stored as float32 (+ tail)

    int tail_n = out_size - IDX_ELEMS;
    if (tail_n < 0) tail_n = 0;

    k_fused<<<BB * CHUNKS, 256>>>(reinterpret_cast<const float4*>(masks),
                                  rand_u, out, tail_n);
}

// round 12
// speedup vs baseline: 1.3854x; 1.3854x over previous
#include <cuda_runtime.h>
#include <stdint.h>

// Problem shape is fixed by setup_inputs(): B=64, N=4, H=512, W=512, num=1024.
#define BB 64
#define NPLANES 4
#define HH 512
#define WW 512
#define HWPIX (HH * WW)            // 262144
#define HW4 (HWPIX / 4)            // 65536 float4s per plane
#define WORDS_PER_B (HWPIX / 32)   // 8192
#define CHUNKS 256                 // chunks per batch; chunk = 32 words = 1024 px
#define NUM 1024
#define IDX_ELEMS (BB * NUM * 2)   // 131072 index values
#define PARTS 16                   // sample blocks per batch (64 points each)

// Scratch (no allocations allowed).
__device__ uint32_t g_bits[BB * WORDS_PER_B];    // 2 MiB  packed valid bits
__device__ int      g_chunk[BB * CHUNKS];        // 64 KiB popcount per chunk

// ---------------------------------------------------------------------------
// Kernel 1: valid[b,p] = (sum_n masks[b,n,p]) > 0.5, packed 32 pixels/word.
// 4 consecutive pixels/thread via float4 (measured 6.66 TB/s, 84% DRAM — at
// the LTS cap). Each block covers exactly one 1024-pixel chunk and emits its
// popcount (measured free in R10). NO fences/atomics — R11 showed a GPU-scope
// fence in this wave costs 26 us of stream throughput.
// ---------------------------------------------------------------------------
__global__ __launch_bounds__(256) void k_mask_bits(const float4* __restrict__ m4) {
    int gid4 = blockIdx.x * 256 + threadIdx.x;   // float4 index in [0, B*HW/4)
    int b  = gid4 >> 16;                         // (gid4*4) / HWPIX
    int p4 = gid4 & (HW4 - 1);
    const float4* base = m4 + (size_t)b * NPLANES * HW4 + p4;
    float4 a0 = base[0];
    float4 a1 = base[HW4];
    float4 a2 = base[2 * HW4];
    float4 a3 = base[3 * HW4];
    // Keep the exact association order that validated bit-exact.
    float sx = ((a0.x + a1.x) + a2.x) + a3.x;
    float sy = ((a0.y + a1.y) + a2.y) + a3.y;
    float sz = ((a0.z + a1.z) + a2.z) + a3.z;
    float sw = ((a0.w + a1.w) + a2.w) + a3.w;
    unsigned nib = (unsigned)(sx > 0.5f)
                 | ((unsigned)(sy > 0.5f) << 1)
                 | ((unsigned)(sz > 0.5f) << 2)
                 | ((unsigned)(sw > 0.5f) << 3);
    int l = threadIdx.x & 31;
    unsigned v = nib << ((l & 7) * 4);
    v |= __shfl_xor_sync(0xFFFFFFFFu, v, 1);
    v |= __shfl_xor_sync(0xFFFFFFFFu, v, 2);
    v |= __shfl_xor_sync(0xFFFFFFFFu, v, 4);
    if ((l & 7) == 0) g_bits[gid4 >> 3] = v;     // word = (4*gid4)/32

    // Chunk popcount: block-wide sum of per-thread nibble popcounts.
    __shared__ int wsum[8];
    int c4 = __popc(nib);
#pragma unroll
    for (int off = 16; off; off >>= 1)
        c4 += __shfl_xor_sync(0xFFFFFFFFu, c4, off);
    if (l == 0) wsum[threadIdx.x >> 5] = c4;
    __syncthreads();
    if (threadIdx.x == 0) {
        int s = 0;
#pragma unroll
        for (int i = 0; i < 8; i++) s += wsum[i];
        g_chunk[blockIdx.x] = s;                 // blockIdx.x = b*CHUNKS + chunk
    }
}

// ---------------------------------------------------------------------------
// Kernel 2: sampling. PARTS=16 blocks per batch (1024 blocks total — one full
// resident wave, ~7 blocks/SM, fixing R10's 20% occupancy). All 256 threads
// run the cheap redundant prologue (1 KB chunk-count load + shuffle scan);
// threads 0..63 then each resolve ONE point: 8-level shared binary search to
// the chunk, one 128 B bit load (MLP=8), flagged popcount select.
// Replicates: r = min(int(u*float(cnt)), cnt-1); pos = searchsorted(csum, r+1).
// ---------------------------------------------------------------------------
__global__ __launch_bounds__(256) void k_sample(const float* __restrict__ rand_u,
                                                float* __restrict__ out,
                                                int tail_n) {
    __shared__ int s_coarse[CHUNKS];     // exclusive csum of chunk counts
    __shared__ int warp_tot[8];
    __shared__ int s_total;
    int b    = blockIdx.x >> 4;          // batch
    int part = blockIdx.x & (PARTS - 1);
    int t = threadIdx.x;
    int lane = t & 31, wid = t >> 5;

    // Prologue: scan 256 chunk counts (one per thread).
    int c = g_chunk[b * CHUNKS + t];
    int v = c;
#pragma unroll
    for (int off = 1; off < 32; off <<= 1) {
        int n = __shfl_up_sync(0xFFFFFFFFu, v, off);
        if (lane >= off) v += n;
    }
    if (lane == 31) warp_tot[wid] = v;
    __syncthreads();
    int wbase = 0;
#pragma unroll
    for (int i = 0; i < 8; i++) wbase += (i < wid) ? warp_tot[i] : 0;
    s_coarse[t] = wbase + v - c;         // bits strictly before chunk t
    if (t == 255) s_total = wbase + v;   // batch total
    __syncthreads();

    // Tail fill ((H, W) tuple leaves flattened into d_out).
    if (blockIdx.x == 0) {
        for (int i = t; i < tail_n; i += 256) out[IDX_ELEMS + i] = 512.0f;
    }

    if (t >= NUM / PARTS) return;        // threads 64..255 done

    int total = s_total;
    int pt = part * (NUM / PARTS) + t;
    float u = rand_u[b * NUM + pt];

    int pos;
    if (total == 0) {
        // reference: cnt = max(total,1) = 1, r = 0, searchsorted over
        // all-zero csum for target 1 -> insertion point HW.
        pos = HWPIX;
    } else {
        int cnt = total;
        int r = (int)(u * (float)cnt);       // fp32 RN mul, trunc — matches jnp
        if (r > cnt - 1) r = cnt - 1;
        int tgt = r + 1;                     // want the tgt-th set bit (1-indexed)

        // Coarse: last chunk with (bits before chunk) < tgt. s_coarse[0]=0<tgt.
        int lo = 0, hi = CHUNKS;
#pragma unroll
        for (int s = 0; s < 8; s++) {
            int mid = (lo + hi) >> 1;
            if (s_coarse[mid] < tgt) lo = mid; else hi = mid;
        }
        int k = tgt - s_coarse[lo];          // k-th set bit within chunk, k>=1

        // Load the chunk's 32 bit-words (128 B, MLP=8) and select the word.
        const uint4* bw = reinterpret_cast<const uint4*>(
            g_bits + (size_t)b * WORDS_PER_B + lo * 32);
        int gi = 0;
        bool found = false;
#pragma unroll
        for (int i = 0; i < 8; i++) {
            uint4 q = bw[i];
            int gs = __popc(q.x) + __popc(q.y) + __popc(q.z) + __popc(q.w);
            if (!found) {
                if (k > gs) k -= gs;
                else { gi = i; found = true; }
            }
        }
        uint4 qq = bw[gi];                   // re-load: L1 hit
        int w2 = 0;
        uint32_t wrd = qq.x;
        int pc = __popc(qq.x);
        if (k > pc) {
            k -= pc; wrd = qq.y; w2 = 1; pc = __popc(qq.y);
            if (k > pc) {
                k -= pc; wrd = qq.z; w2 = 2; pc = __popc(qq.z);
                if (k > pc) { k -= pc; wrd = qq.w; w2 = 3; }
            }
        }
        // Fixed-depth 5-step binary select of the k-th set bit (1-indexed).
        int idx = 0;
        int cc = __popc(wrd & 0xFFFFu);
        if (k > cc) { k -= cc; idx += 16; wrd >>= 16; }
        cc = __popc(wrd & 0xFFu);
        if (k > cc) { k -= cc; idx += 8; wrd >>= 8; }
        cc = __popc(wrd & 0xFu);
        if (k > cc) { k -= cc; idx += 4; wrd >>= 4; }
        cc = __popc(wrd & 0x3u);
        if (k > cc) { k -= cc; idx += 2; wrd >>= 2; }
        cc = wrd & 1u;
        if (k > cc) { idx += 1; }
        pos = lo * 1024 + (gi * 4 + w2) * 32 + idx;
    }

    float2 hw;
    hw.x = (float)(pos / WW);
    hw.y = (float)(pos & (WW - 1));
    *reinterpret_cast<float2*>(out + ((size_t)b * NUM + pt) * 2) = hw;
}

extern "C" void kernel_launch(void* const* d_in, const int* in_sizes, int n_in,
                              void* d_out, int out_size) {
    // Identify inputs by size, robust to metadata ordering.
    const float* masks  = nullptr;   // [64,4,512,512] f32 -> 67,108,864 elems
    const float* rand_u = nullptr;   // [64,1024] f32      -> 65,536 elems
    for (int i = 0; i < n_in; i++) {
        if (in_sizes[i] == BB * NPLANES * HWPIX) masks = (const float*)d_in[i];
        else if (in_sizes[i] == BB * NUM)        rand_u = (const float*)d_in[i];
    }
    if (!masks)  masks  = (const float*)d_in[0];
    if (!rand_u) rand_u = (const float*)d_in[1];
    float* out = (float*)d_out;      // [64,1024,2] stored as float32 (+ tail)

    int tail_n = out_size - IDX_ELEMS;
    if (tail_n < 0) tail_n = 0;

    k_mask_bits<<<(BB * HW4) / 256, 256>>>(reinterpret_cast<const float4*>(masks));
    k_sample<<<BB * PARTS, 256>>>(rand_u, out, tail_n);
}